// round 13
// baseline (speedup 1.0000x reference)
#include <cuda_runtime.h>
#include <cuda_fp16.h>
#include <cstdint>

#define N_NODES 50000
#define FEATS   64
#define N_EDGES 800000
#define CAP     128       // per-node neighbor capacity (Poisson λ=16; P(>=128)≈0)
#define STW     36        // smem row stride in WORDS (=72 halfs)
#define NTILE   ((N_NODES + 127) >> 7)              // 391 tiles of 128 nodes

// -------- scratch (device globals; no allocation allowed) --------
__device__ int g_idx32;
__device__ int g_fill[N_NODES];         // slot counter == degree after fill
__device__ int g_colpad[N_NODES * CAP]; // padded neighbor lists
__device__ __align__(16) float g_h1 [N_NODES * FEATS];
__device__ __align__(16) float g_h2 [N_NODES * FEATS];

// -------- prep 1: zero fill counters + dtype detect --------
// item_ids == arange: int32 words 0,1,2,... -> word[2]==2 ; int64 -> word[2]==1
__global__ void k_zero(const int* ids_words) {
    int i = blockIdx.x * blockDim.x + threadIdx.x;
    if (i == 0) g_idx32 = (ids_words[2] == 2) ? 1 : 0;
    if (i < N_NODES) g_fill[i] = 0;
}

__device__ __forceinline__ int read_idx(const void* p, int i) {
    return g_idx32 ? ((const int*)p)[i] : (int)((const long long*)p)[i];
}

// -------- prep 2: single-pass bucket fill --------
__global__ void k_fill(const void* __restrict__ src, const void* __restrict__ dst) {
    int i = blockIdx.x * blockDim.x + threadIdx.x;
    if (i >= N_EDGES) return;
    int d = read_idx(dst, i);
    int s = read_idx(src, i);
    int slot = atomicAdd(&g_fill[d], 1);
    if (slot < CAP) g_colpad[d * CAP + slot] = s;
}

// -------- fp16 m16n8k16 MMA --------
__device__ __forceinline__ void mma16(float* d,
                                      unsigned a0, unsigned a1, unsigned a2, unsigned a3,
                                      unsigned b0, unsigned b1) {
    asm volatile(
        "mma.sync.aligned.m16n8k16.row.col.f32.f16.f16.f32 "
        "{%0,%1,%2,%3}, {%4,%5,%6,%7}, {%8,%9}, {%0,%1,%2,%3};"
        : "+f"(d[0]), "+f"(d[1]), "+f"(d[2]), "+f"(d[3])
        : "r"(a0), "r"(a1), "r"(a2), "r"(a3), "r"(b0), "r"(b1));
}

// -------- staging helpers (shared by both kernels) --------
__device__ __forceinline__ void stage_weightT(unsigned* sW, const float* __restrict__ W,
                                              int tid) {
    __half* sW_h = (__half*)sW;
    for (int i = tid; i < 64 * 16; i += 256) {
        int k = i >> 4, n4 = (i & 15) * 4;
        float4 v = ((const float4*)W)[i];
        sW_h[(n4 + 0) * (2 * STW) + k] = __float2half_rn(v.x);
        sW_h[(n4 + 1) * (2 * STW) + k] = __float2half_rn(v.y);
        sW_h[(n4 + 2) * (2 * STW) + k] = __float2half_rn(v.z);
        sW_h[(n4 + 3) * (2 * STW) + k] = __float2half_rn(v.w);
    }
}

__device__ __forceinline__ void stage_tile(unsigned* sH, const float* __restrict__ H,
                                           int n0node, int tid) {
    for (int i = tid; i < 128 * 16; i += 256) {
        int r = i >> 4, c = i & 15;
        int gr = n0node + r;
        bool ok = (gr < N_NODES);
        float4 v = ok ? ((const float4*)H)[gr * 16 + c] : make_float4(0.f, 0.f, 0.f, 0.f);
        __half2 lo = __floats2half2_rn(v.x, v.y);
        __half2 hi = __floats2half2_rn(v.z, v.w);
        sH[r * STW + c * 2]     = *(unsigned*)&lo;
        sH[r * STW + c * 2 + 1] = *(unsigned*)&hi;
    }
}

// -------- fused SAGE layer: per-tile agg (R5-proven loop) + fp16 MMA --------
template <bool RELU>
__global__ void __launch_bounds__(256)
k_fused(const float* __restrict__ H,
        const float* __restrict__ Ws, const float* __restrict__ Wn,
        const float* __restrict__ bias, float* __restrict__ C) {
    extern __shared__ unsigned sm[];
    unsigned* sWs = sm;                      // 64*STW words
    unsigned* sWn = sm + 64 * STW;
    unsigned* sH  = sm + 2 * 64 * STW;       // 128*STW
    unsigned* sG  = sH + 128 * STW;          // 128*STW

    int tid = threadIdx.x;
    int lane = tid & 31, wid = tid >> 5;
    int n0node = blockIdx.x << 7;

    stage_weightT(sWs, Ws, tid);
    stage_weightT(sWn, Wn, tid);
    stage_tile(sH, H, n0node, tid);

    // fused aggregation: warp wid owns tile rows [wid*16, wid*16+16)
    // inner loop = byte-identical R5 proven shape; result -> sG fp16
    const float2* h2 = (const float2*)H;
    for (int r = wid * 16; r < wid * 16 + 16; r++) {
        int node = n0node + r;
        float2 a0 = make_float2(0.f, 0.f), a1 = make_float2(0.f, 0.f);
        float inv = 0.0f;
        if (node < N_NODES) {
            int deg = g_fill[node];
            int e = (deg < CAP) ? deg : CAP;
            const int* col = g_colpad + node * CAP;
            int j = 0;
            for (; j + 1 < e; j += 2) {
                int c0 = col[j], c1 = col[j + 1];
                float2 v0 = h2[c0 * 32 + lane];
                float2 v1 = h2[c1 * 32 + lane];
                a0.x += v0.x; a0.y += v0.y;
                a1.x += v1.x; a1.y += v1.y;
            }
            if (j < e) {
                int c = col[j];
                float2 v = h2[c * 32 + lane];
                a0.x += v.x; a0.y += v.y;
            }
            inv = (deg > 0) ? (1.0f / (float)deg) : 0.0f;
        }
        __half2 o = __floats2half2_rn((a0.x + a1.x) * inv, (a0.y + a1.y) * inv);
        sG[r * STW + lane] = *(unsigned*)&o;
    }
    __syncthreads();

    int gID = lane >> 2;
    int tg  = lane & 3;
    int mb  = wid << 4;

    float acc[8][4];
    #pragma unroll
    for (int n = 0; n < 8; n++) {
        float b0 = bias[n * 8 + tg * 2];
        float b1 = bias[n * 8 + tg * 2 + 1];
        acc[n][0] = b0; acc[n][1] = b1; acc[n][2] = b0; acc[n][3] = b1;
    }

    #pragma unroll
    for (int ks = 0; ks < 4; ks++) {
        int kw = ks * 8;
        const unsigned* ah = sH + (mb + gID) * STW + kw + tg;
        unsigned ha0 = ah[0], ha1 = ah[8 * STW], ha2 = ah[4], ha3 = ah[8 * STW + 4];
        const unsigned* ag = sG + (mb + gID) * STW + kw + tg;
        unsigned ga0 = ag[0], ga1 = ag[8 * STW], ga2 = ag[4], ga3 = ag[8 * STW + 4];
        #pragma unroll
        for (int n = 0; n < 8; n++) {
            const unsigned* bw = sWs + (n * 8 + gID) * STW + kw + tg;
            mma16(acc[n], ha0, ha1, ha2, ha3, bw[0], bw[4]);
            const unsigned* bn = sWn + (n * 8 + gID) * STW + kw + tg;
            mma16(acc[n], ga0, ga1, ga2, ga3, bn[0], bn[4]);
        }
    }

    int r0 = n0node + mb + gID;
    int r1 = r0 + 8;
    #pragma unroll
    for (int n = 0; n < 8; n++) {
        int c = n * 8 + tg * 2;
        float2 v0, v1;
        v0.x = RELU ? fmaxf(acc[n][0], 0.f) : acc[n][0];
        v0.y = RELU ? fmaxf(acc[n][1], 0.f) : acc[n][1];
        v1.x = RELU ? fmaxf(acc[n][2], 0.f) : acc[n][2];
        v1.y = RELU ? fmaxf(acc[n][3], 0.f) : acc[n][3];
        if (r0 < N_NODES) *(float2*)(C + r0 * 64 + c) = v0;
        if (r1 < N_NODES) *(float2*)(C + r1 * 64 + c) = v1;
    }
}

// -------- final linear (no neighbor term), fp16 MMA --------
__global__ void __launch_bounds__(256)
k_final(const float* __restrict__ H, const float* __restrict__ W,
        const float* __restrict__ bias, float* __restrict__ C) {
    extern __shared__ unsigned sm[];
    unsigned* sW = sm;                       // 64*STW
    unsigned* sH = sm + 64 * STW;            // 128*STW

    int tid = threadIdx.x;
    int lane = tid & 31, wid = tid >> 5;
    int n0node = blockIdx.x << 7;

    stage_weightT(sW, W, tid);
    stage_tile(sH, H, n0node, tid);
    __syncthreads();

    int gID = lane >> 2;
    int tg  = lane & 3;
    int mb  = wid << 4;

    float acc[8][4];
    #pragma unroll
    for (int n = 0; n < 8; n++) {
        float b0 = bias[n * 8 + tg * 2];
        float b1 = bias[n * 8 + tg * 2 + 1];
        acc[n][0] = b0; acc[n][1] = b1; acc[n][2] = b0; acc[n][3] = b1;
    }

    #pragma unroll
    for (int ks = 0; ks < 4; ks++) {
        int kw = ks * 8;
        const unsigned* ah = sH + (mb + gID) * STW + kw + tg;
        unsigned ha0 = ah[0], ha1 = ah[8 * STW], ha2 = ah[4], ha3 = ah[8 * STW + 4];
        #pragma unroll
        for (int n = 0; n < 8; n++) {
            const unsigned* bw = sW + (n * 8 + gID) * STW + kw + tg;
            mma16(acc[n], ha0, ha1, ha2, ha3, bw[0], bw[4]);
        }
    }

    int r0 = n0node + mb + gID;
    int r1 = r0 + 8;
    #pragma unroll
    for (int n = 0; n < 8; n++) {
        int c = n * 8 + tg * 2;
        if (r0 < N_NODES) *(float2*)(C + r0 * 64 + c) = make_float2(acc[n][0], acc[n][1]);
        if (r1 < N_NODES) *(float2*)(C + r1 * 64 + c) = make_float2(acc[n][2], acc[n][3]);
    }
}

extern "C" void kernel_launch(void* const* d_in, const int* in_sizes, int n_in,
                              void* d_out, int out_size) {
    const float* embed   = (const float*)d_in[0];
    const float* W1_self = (const float*)d_in[1];
    const float* W1_neigh= (const float*)d_in[2];
    const float* b1      = (const float*)d_in[3];
    const float* W2_self = (const float*)d_in[4];
    const float* W2_neigh= (const float*)d_in[5];
    const float* b2      = (const float*)d_in[6];
    const float* W_fc    = (const float*)d_in[7];
    const float* b_fc    = (const float*)d_in[8];
    const int*   ids_w   = (const int*)d_in[9];
    const void*  src     = d_in[10];
    const void*  dst     = d_in[11];
    float* out = (float*)d_out;

    const int SMEM_N = (2 * 64 * STW + 2 * 128 * STW) * 4;   // 55296 B
    const int SMEM_F = (64 * STW + 128 * STW) * 4;           // 27648 B
    cudaFuncSetAttribute((const void*)k_fused<true>,
                         cudaFuncAttributeMaxDynamicSharedMemorySize, SMEM_N);
    cudaFuncSetAttribute((const void*)k_fused<false>,
                         cudaFuncAttributeMaxDynamicSharedMemorySize, SMEM_N);
    cudaFuncSetAttribute((const void*)k_final,
                         cudaFuncAttributeMaxDynamicSharedMemorySize, SMEM_F);

    float* h1; cudaGetSymbolAddress((void**)&h1, g_h1);
    float* h2; cudaGetSymbolAddress((void**)&h2, g_h2);

    // --- prep: 2 launches (padded buckets) ---
    k_zero<<<(N_NODES + 255) / 256, 256>>>(ids_w);
    k_fill<<<(N_EDGES + 255) / 256, 256>>>(src, dst);

    // --- Layer 1 (fused agg+transform) ---
    k_fused<true><<<NTILE, 256, SMEM_N>>>(embed, W1_self, W1_neigh, b1, h1);

    // --- Layer 2 (launch idx 3 -> ncu target) ---
    k_fused<false><<<NTILE, 256, SMEM_N>>>(h1, W2_self, W2_neigh, b2, h2);

    // --- Final linear ---
    k_final<<<NTILE, 256, SMEM_F>>>(h2, W_fc, b_fc, out);
}

// round 14
// speedup vs baseline: 1.6691x; 1.6691x over previous
#include <cuda_runtime.h>
#include <cuda_fp16.h>
#include <cstdint>

#define N_NODES 50000
#define FEATS   64
#define N_EDGES 800000
#define CAP     128       // per-node neighbor capacity (Poisson λ=16; P(>=128)≈0)
#define STW     36        // smem row stride in WORDS (=72 halfs)
#define NTILE   ((N_NODES + 127) >> 7)              // 391 tiles of 128 nodes

// -------- scratch (device globals; no allocation allowed) --------
__device__ int g_idx32;
__device__ int g_fill[N_NODES];
__device__ int g_colpad[N_NODES * CAP];
__device__ __align__(16) __half2 g_xh  [N_NODES * 32];  // embed, fp16
__device__ __align__(16) __half2 g_aggh[N_NODES * 32];  // agg output, fp16
__device__ __align__(16) __half2 g_h1h [N_NODES * 32];  // h1, fp16
__device__ __align__(16) __half2 g_h2h [N_NODES * 32];  // h2, fp16

// -------- prep 1: zero counters + dtype detect + embed->fp16 --------
// item_ids == arange: int32 words 0,1,2,... -> word[2]==2 ; int64 -> word[2]==1
__global__ void k_zero(const int* ids_words, const float* __restrict__ embed) {
    int i = blockIdx.x * blockDim.x + threadIdx.x;
    if (i == 0) g_idx32 = (ids_words[2] == 2) ? 1 : 0;
    if (i < N_NODES) g_fill[i] = 0;
    if (i < N_NODES * 32) {
        float2 v = ((const float2*)embed)[i];
        g_xh[i] = __floats2half2_rn(v.x, v.y);
    }
}

__device__ __forceinline__ int read_idx(const void* p, int i) {
    return g_idx32 ? ((const int*)p)[i] : (int)((const long long*)p)[i];
}

// -------- prep 2: single-pass bucket fill --------
__global__ void k_fill(const void* __restrict__ src, const void* __restrict__ dst) {
    int i = blockIdx.x * blockDim.x + threadIdx.x;
    if (i >= N_EDGES) return;
    int d = read_idx(dst, i);
    int s = read_idx(src, i);
    int slot = atomicAdd(&g_fill[d], 1);
    if (slot < CAP) g_colpad[d * CAP + slot] = s;
}

// -------- mean aggregation (R5-proven loop shape, fp16 gather) --------
__global__ void k_agg(const __half2* __restrict__ h2, __half2* __restrict__ agg) {
    int warp = (blockIdx.x * blockDim.x + threadIdx.x) >> 5;
    int lane = threadIdx.x & 31;
    if (warp >= N_NODES) return;
    int deg = g_fill[warp];
    int e = (deg < CAP) ? deg : CAP;
    const int* col = g_colpad + warp * CAP;
    float2 a0 = make_float2(0.f, 0.f), a1 = make_float2(0.f, 0.f);
    int j = 0;
    for (; j + 1 < e; j += 2) {
        int c0 = col[j], c1 = col[j + 1];
        float2 v0 = __half22float2(h2[c0 * 32 + lane]);
        float2 v1 = __half22float2(h2[c1 * 32 + lane]);
        a0.x += v0.x; a0.y += v0.y;
        a1.x += v1.x; a1.y += v1.y;
    }
    if (j < e) {
        int c = col[j];
        float2 v = __half22float2(h2[c * 32 + lane]);
        a0.x += v.x; a0.y += v.y;
    }
    float inv = (deg > 0) ? (1.0f / (float)deg) : 0.0f;
    agg[warp * 32 + lane] =
        __floats2half2_rn((a0.x + a1.x) * inv, (a0.y + a1.y) * inv);
}

// -------- fp16 m16n8k16 MMA --------
__device__ __forceinline__ void mma16(float* d,
                                      unsigned a0, unsigned a1, unsigned a2, unsigned a3,
                                      unsigned b0, unsigned b1) {
    asm volatile(
        "mma.sync.aligned.m16n8k16.row.col.f32.f16.f16.f32 "
        "{%0,%1,%2,%3}, {%4,%5,%6,%7}, {%8,%9}, {%0,%1,%2,%3};"
        : "+f"(d[0]), "+f"(d[1]), "+f"(d[2]), "+f"(d[3])
        : "r"(a0), "r"(a1), "r"(a2), "r"(a3), "r"(b0), "r"(b1));
}

// stage weights TRANSPOSED: W[k][n] f32 -> sW[n-row][k] halfs
__device__ __forceinline__ void stage_weightT(unsigned* sW, const float* __restrict__ W,
                                              int tid) {
    __half* sW_h = (__half*)sW;
    for (int i = tid; i < 64 * 16; i += 256) {
        int k = i >> 4, n4 = (i & 15) * 4;
        float4 v = ((const float4*)W)[i];
        sW_h[(n4 + 0) * (2 * STW) + k] = __float2half_rn(v.x);
        sW_h[(n4 + 1) * (2 * STW) + k] = __float2half_rn(v.y);
        sW_h[(n4 + 2) * (2 * STW) + k] = __float2half_rn(v.z);
        sW_h[(n4 + 3) * (2 * STW) + k] = __float2half_rn(v.w);
    }
}

// stage a 128-row fp16 tile: raw uint4 copy, no conversion
__device__ __forceinline__ void stage_tile16(unsigned* sH, const __half2* __restrict__ Hh,
                                             int n0node, int tid) {
    for (int i = tid; i < 128 * 8; i += 256) {
        int r = i >> 3, c = i & 7;          // c = uint4 index within row (8 per row)
        int gr = n0node + r;
        uint4 v = (gr < N_NODES) ? ((const uint4*)Hh)[gr * 8 + c]
                                 : make_uint4(0u, 0u, 0u, 0u);
        ((uint4*)(sH + r * STW))[c] = v;
    }
}

template <bool NEIGH, bool RELU, bool OUTF16>
__global__ void __launch_bounds__(256)
k_mma(const __half2* __restrict__ H, const __half2* __restrict__ G,
      const float* __restrict__ Ws, const float* __restrict__ Wn,
      const float* __restrict__ bias, void* __restrict__ Cv) {
    extern __shared__ unsigned sm[];
    unsigned* sWs = sm;                                      // 64*STW words
    unsigned* sWn = NEIGH ? (sm + 64 * STW) : nullptr;
    unsigned* sH  = NEIGH ? (sm + 2 * 64 * STW) : (sm + 64 * STW);  // 128*STW
    unsigned* sG  = NEIGH ? (sH + 128 * STW) : nullptr;

    int tid = threadIdx.x;
    int lane = tid & 31, wid = tid >> 5;
    int n0node = blockIdx.x << 7;

    stage_weightT(sWs, Ws, tid);
    if (NEIGH) stage_weightT(sWn, Wn, tid);
    stage_tile16(sH, H, n0node, tid);
    if (NEIGH) stage_tile16(sG, G, n0node, tid);
    __syncthreads();

    int gID = lane >> 2;
    int tg  = lane & 3;
    int mb  = wid << 4;

    float acc[8][4];
    #pragma unroll
    for (int n = 0; n < 8; n++) {
        float b0 = bias[n * 8 + tg * 2];
        float b1 = bias[n * 8 + tg * 2 + 1];
        acc[n][0] = b0; acc[n][1] = b1; acc[n][2] = b0; acc[n][3] = b1;
    }

    #pragma unroll
    for (int ks = 0; ks < 4; ks++) {
        int kw = ks * 8;
        const unsigned* ah = sH + (mb + gID) * STW + kw + tg;
        unsigned ha0 = ah[0], ha1 = ah[8 * STW], ha2 = ah[4], ha3 = ah[8 * STW + 4];
        unsigned ga0 = 0, ga1 = 0, ga2 = 0, ga3 = 0;
        if (NEIGH) {
            const unsigned* ag = sG + (mb + gID) * STW + kw + tg;
            ga0 = ag[0]; ga1 = ag[8 * STW]; ga2 = ag[4]; ga3 = ag[8 * STW + 4];
        }
        #pragma unroll
        for (int n = 0; n < 8; n++) {
            const unsigned* bw = sWs + (n * 8 + gID) * STW + kw + tg;
            mma16(acc[n], ha0, ha1, ha2, ha3, bw[0], bw[4]);
            if (NEIGH) {
                const unsigned* bn = sWn + (n * 8 + gID) * STW + kw + tg;
                mma16(acc[n], ga0, ga1, ga2, ga3, bn[0], bn[4]);
            }
        }
    }

    int r0 = n0node + mb + gID;
    int r1 = r0 + 8;
    #pragma unroll
    for (int n = 0; n < 8; n++) {
        int c = n * 8 + tg * 2;
        float2 v0, v1;
        v0.x = RELU ? fmaxf(acc[n][0], 0.f) : acc[n][0];
        v0.y = RELU ? fmaxf(acc[n][1], 0.f) : acc[n][1];
        v1.x = RELU ? fmaxf(acc[n][2], 0.f) : acc[n][2];
        v1.y = RELU ? fmaxf(acc[n][3], 0.f) : acc[n][3];
        if (OUTF16) {
            __half2* C = (__half2*)Cv;
            if (r0 < N_NODES) C[r0 * 32 + (c >> 1)] = __floats2half2_rn(v0.x, v0.y);
            if (r1 < N_NODES) C[r1 * 32 + (c >> 1)] = __floats2half2_rn(v1.x, v1.y);
        } else {
            float* C = (float*)Cv;
            if (r0 < N_NODES) *(float2*)(C + r0 * 64 + c) = v0;
            if (r1 < N_NODES) *(float2*)(C + r1 * 64 + c) = v1;
        }
    }
}

extern "C" void kernel_launch(void* const* d_in, const int* in_sizes, int n_in,
                              void* d_out, int out_size) {
    const float* embed   = (const float*)d_in[0];
    const float* W1_self = (const float*)d_in[1];
    const float* W1_neigh= (const float*)d_in[2];
    const float* b1      = (const float*)d_in[3];
    const float* W2_self = (const float*)d_in[4];
    const float* W2_neigh= (const float*)d_in[5];
    const float* b2      = (const float*)d_in[6];
    const float* W_fc    = (const float*)d_in[7];
    const float* b_fc    = (const float*)d_in[8];
    const int*   ids_w   = (const int*)d_in[9];
    const void*  src     = d_in[10];
    const void*  dst     = d_in[11];
    float* out = (float*)d_out;

    const int SMEM_N = (2 * 64 * STW + 2 * 128 * STW) * 4;   // 55296 B
    const int SMEM_F = (64 * STW + 128 * STW) * 4;           // 27648 B
    cudaFuncSetAttribute((const void*)k_mma<true, true, true>,
                         cudaFuncAttributeMaxDynamicSharedMemorySize, SMEM_N);
    cudaFuncSetAttribute((const void*)k_mma<true, false, true>,
                         cudaFuncAttributeMaxDynamicSharedMemorySize, SMEM_N);
    cudaFuncSetAttribute((const void*)k_mma<false, false, false>,
                         cudaFuncAttributeMaxDynamicSharedMemorySize, SMEM_F);

    __half2* xh;   cudaGetSymbolAddress((void**)&xh,   g_xh);
    __half2* aggh; cudaGetSymbolAddress((void**)&aggh, g_aggh);
    __half2* h1h;  cudaGetSymbolAddress((void**)&h1h,  g_h1h);
    __half2* h2h;  cudaGetSymbolAddress((void**)&h2h,  g_h2h);

    // --- prep: zero+cvt, bucket fill ---
    k_zero<<<(N_NODES * 32 + 255) / 256, 256>>>(ids_w, embed);
    k_fill<<<(N_EDGES + 255) / 256, 256>>>(src, dst);

    const int AGG_BLOCKS = (N_NODES * 32 + 255) / 256;

    // --- Layer 1 ---
    k_agg<<<AGG_BLOCKS, 256>>>(xh, aggh);
    k_mma<true, true, true><<<NTILE, 256, SMEM_N>>>(
        xh, aggh, W1_self, W1_neigh, b1, h1h);

    // --- Layer 2 ---
    k_agg<<<AGG_BLOCKS, 256>>>(h1h, aggh);
    k_mma<true, false, true><<<NTILE, 256, SMEM_N>>>(
        h1h, aggh, W2_self, W2_neigh, b2, h2h);

    // --- Final linear (f32 output) ---
    k_mma<false, false, false><<<NTILE, 256, SMEM_F>>>(
        h2h, nullptr, W_fc, nullptr, b_fc, out);
}

// round 15
// speedup vs baseline: 1.7700x; 1.0605x over previous
#include <cuda_runtime.h>
#include <cuda_fp16.h>
#include <cstdint>

#define N_NODES 50000
#define FEATS   64
#define N_EDGES 800000
#define CAP     128       // per-node neighbor capacity (Poisson λ=16; P(>=128)≈0)
#define STW     36        // smem row stride in WORDS (=72 halfs)
#define NTILE   ((N_NODES + 127) >> 7)              // 391 tiles of 128 nodes
#define WTILE   (64 * STW)                          // words per staged weight tile

// -------- scratch (device globals; no allocation allowed) --------
__device__ int g_idx32;
__device__ int g_fill[N_NODES];
__device__ __align__(16) int g_colpad[N_NODES * CAP];
__device__ __align__(16) unsigned g_wt[5 * WTILE];      // fp16 transposed weights
__device__ __align__(16) __half2 g_xh  [N_NODES * 32];  // embed, fp16
__device__ __align__(16) __half2 g_aggh[N_NODES * 32];  // agg output, fp16
__device__ __align__(16) __half2 g_h1h [N_NODES * 32];  // h1, fp16
__device__ __align__(16) __half2 g_h2h [N_NODES * 32];  // h2, fp16

// -------- prep 1: zero + dtype detect + embed->fp16 + weights->fp16T --------
// item_ids == arange: int32 words 0,1,2,... -> word[2]==2 ; int64 -> word[2]==1
__global__ void k_zero(const int* ids_words, const float* __restrict__ embed,
                       const float* __restrict__ W1s, const float* __restrict__ W1n,
                       const float* __restrict__ W2s, const float* __restrict__ W2n,
                       const float* __restrict__ Wfc) {
    int i = blockIdx.x * blockDim.x + threadIdx.x;
    if (i == 0) g_idx32 = (ids_words[2] == 2) ? 1 : 0;
    if (i < N_NODES) g_fill[i] = 0;
    if (i < N_NODES * 32) {
        float2 v = ((const float2*)embed)[i];
        g_xh[i] = __floats2half2_rn(v.x, v.y);
    }
    // convert 5 weight matrices: W[k][n] f32 -> g_wt[w][n-row][k] halfs
    if (i < 5 * 1024) {
        int w = i >> 10, e = i & 1023;
        const float* W = (w == 0) ? W1s : (w == 1) ? W1n : (w == 2) ? W2s
                       : (w == 3) ? W2n : Wfc;
        int k = e >> 4, n4 = (e & 15) * 4;
        float4 v = ((const float4*)W)[e];
        __half* dst = (__half*)(g_wt + w * WTILE);
        dst[(n4 + 0) * (2 * STW) + k] = __float2half_rn(v.x);
        dst[(n4 + 1) * (2 * STW) + k] = __float2half_rn(v.y);
        dst[(n4 + 2) * (2 * STW) + k] = __float2half_rn(v.z);
        dst[(n4 + 3) * (2 * STW) + k] = __float2half_rn(v.w);
    }
}

__device__ __forceinline__ int read_idx(const void* p, int i) {
    return g_idx32 ? ((const int*)p)[i] : (int)((const long long*)p)[i];
}

// -------- prep 2: single-pass bucket fill --------
__global__ void k_fill(const void* __restrict__ src, const void* __restrict__ dst) {
    int i = blockIdx.x * blockDim.x + threadIdx.x;
    if (i >= N_EDGES) return;
    int d = read_idx(dst, i);
    int s = read_idx(src, i);
    int slot = atomicAdd(&g_fill[d], 1);
    if (slot < CAP) g_colpad[d * CAP + slot] = s;
}

// -------- mean aggregation: R5 loop shape + int2 col loads (j stays even) --------
__global__ void k_agg(const __half2* __restrict__ h2, __half2* __restrict__ agg) {
    int warp = (blockIdx.x * blockDim.x + threadIdx.x) >> 5;
    int lane = threadIdx.x & 31;
    if (warp >= N_NODES) return;
    int deg = g_fill[warp];
    int e = (deg < CAP) ? deg : CAP;
    const int* col = g_colpad + warp * CAP;    // 512B-aligned
    float2 a0 = make_float2(0.f, 0.f), a1 = make_float2(0.f, 0.f);
    int j = 0;
    for (; j + 1 < e; j += 2) {
        int2 cc = *(const int2*)&col[j];       // one LDG.64 broadcast, 2 indices
        float2 v0 = __half22float2(h2[cc.x * 32 + lane]);
        float2 v1 = __half22float2(h2[cc.y * 32 + lane]);
        a0.x += v0.x; a0.y += v0.y;
        a1.x += v1.x; a1.y += v1.y;
    }
    if (j < e) {
        int c = col[j];
        float2 v = __half22float2(h2[c * 32 + lane]);
        a0.x += v.x; a0.y += v.y;
    }
    float inv = (deg > 0) ? (1.0f / (float)deg) : 0.0f;
    agg[warp * 32 + lane] =
        __floats2half2_rn((a0.x + a1.x) * inv, (a0.y + a1.y) * inv);
}

// -------- fp16 m16n8k16 MMA --------
__device__ __forceinline__ void mma16(float* d,
                                      unsigned a0, unsigned a1, unsigned a2, unsigned a3,
                                      unsigned b0, unsigned b1) {
    asm volatile(
        "mma.sync.aligned.m16n8k16.row.col.f32.f16.f16.f32 "
        "{%0,%1,%2,%3}, {%4,%5,%6,%7}, {%8,%9}, {%0,%1,%2,%3};"
        : "+f"(d[0]), "+f"(d[1]), "+f"(d[2]), "+f"(d[3])
        : "r"(a0), "r"(a1), "r"(a2), "r"(a3), "r"(b0), "r"(b1));
}

// stage pre-converted weight tile: raw uint4 copy (576 uint4)
__device__ __forceinline__ void stage_weight_raw(unsigned* sW, const unsigned* __restrict__ wt,
                                                 int tid) {
    for (int i = tid; i < WTILE / 4; i += 256)
        ((uint4*)sW)[i] = ((const uint4*)wt)[i];
}

// stage a 128-row fp16 tile: raw uint4 copy
__device__ __forceinline__ void stage_tile16(unsigned* sH, const __half2* __restrict__ Hh,
                                             int n0node, int tid) {
    for (int i = tid; i < 128 * 8; i += 256) {
        int r = i >> 3, c = i & 7;
        int gr = n0node + r;
        uint4 v = (gr < N_NODES) ? ((const uint4*)Hh)[gr * 8 + c]
                                 : make_uint4(0u, 0u, 0u, 0u);
        ((uint4*)(sH + r * STW))[c] = v;
    }
}

template <bool NEIGH, bool RELU, bool OUTF16>
__global__ void __launch_bounds__(256)
k_mma(const __half2* __restrict__ H, const __half2* __restrict__ G,
      const unsigned* __restrict__ wts, const unsigned* __restrict__ wtn,
      const float* __restrict__ bias, void* __restrict__ Cv) {
    extern __shared__ unsigned sm[];
    unsigned* sWs = sm;                                      // WTILE words
    unsigned* sWn = NEIGH ? (sm + WTILE) : nullptr;
    unsigned* sH  = NEIGH ? (sm + 2 * WTILE) : (sm + WTILE); // 128*STW
    unsigned* sG  = NEIGH ? (sH + 128 * STW) : nullptr;

    int tid = threadIdx.x;
    int lane = tid & 31, wid = tid >> 5;
    int n0node = blockIdx.x << 7;

    stage_weight_raw(sWs, wts, tid);
    if (NEIGH) stage_weight_raw(sWn, wtn, tid);
    stage_tile16(sH, H, n0node, tid);
    if (NEIGH) stage_tile16(sG, G, n0node, tid);
    __syncthreads();

    int gID = lane >> 2;
    int tg  = lane & 3;
    int mb  = wid << 4;

    float acc[8][4];
    #pragma unroll
    for (int n = 0; n < 8; n++) {
        float b0 = bias[n * 8 + tg * 2];
        float b1 = bias[n * 8 + tg * 2 + 1];
        acc[n][0] = b0; acc[n][1] = b1; acc[n][2] = b0; acc[n][3] = b1;
    }

    #pragma unroll
    for (int ks = 0; ks < 4; ks++) {
        int kw = ks * 8;
        const unsigned* ah = sH + (mb + gID) * STW + kw + tg;
        unsigned ha0 = ah[0], ha1 = ah[8 * STW], ha2 = ah[4], ha3 = ah[8 * STW + 4];
        unsigned ga0 = 0, ga1 = 0, ga2 = 0, ga3 = 0;
        if (NEIGH) {
            const unsigned* ag = sG + (mb + gID) * STW + kw + tg;
            ga0 = ag[0]; ga1 = ag[8 * STW]; ga2 = ag[4]; ga3 = ag[8 * STW + 4];
        }
        #pragma unroll
        for (int n = 0; n < 8; n++) {
            const unsigned* bw = sWs + (n * 8 + gID) * STW + kw + tg;
            mma16(acc[n], ha0, ha1, ha2, ha3, bw[0], bw[4]);
            if (NEIGH) {
                const unsigned* bn = sWn + (n * 8 + gID) * STW + kw + tg;
                mma16(acc[n], ga0, ga1, ga2, ga3, bn[0], bn[4]);
            }
        }
    }

    int r0 = n0node + mb + gID;
    int r1 = r0 + 8;
    #pragma unroll
    for (int n = 0; n < 8; n++) {
        int c = n * 8 + tg * 2;
        float2 v0, v1;
        v0.x = RELU ? fmaxf(acc[n][0], 0.f) : acc[n][0];
        v0.y = RELU ? fmaxf(acc[n][1], 0.f) : acc[n][1];
        v1.x = RELU ? fmaxf(acc[n][2], 0.f) : acc[n][2];
        v1.y = RELU ? fmaxf(acc[n][3], 0.f) : acc[n][3];
        if (OUTF16) {
            __half2* C = (__half2*)Cv;
            if (r0 < N_NODES) C[r0 * 32 + (c >> 1)] = __floats2half2_rn(v0.x, v0.y);
            if (r1 < N_NODES) C[r1 * 32 + (c >> 1)] = __floats2half2_rn(v1.x, v1.y);
        } else {
            float* C = (float*)Cv;
            if (r0 < N_NODES) *(float2*)(C + r0 * 64 + c) = v0;
            if (r1 < N_NODES) *(float2*)(C + r1 * 64 + c) = v1;
        }
    }
}

extern "C" void kernel_launch(void* const* d_in, const int* in_sizes, int n_in,
                              void* d_out, int out_size) {
    const float* embed   = (const float*)d_in[0];
    const float* W1_self = (const float*)d_in[1];
    const float* W1_neigh= (const float*)d_in[2];
    const float* b1      = (const float*)d_in[3];
    const float* W2_self = (const float*)d_in[4];
    const float* W2_neigh= (const float*)d_in[5];
    const float* b2      = (const float*)d_in[6];
    const float* W_fc    = (const float*)d_in[7];
    const float* b_fc    = (const float*)d_in[8];
    const int*   ids_w   = (const int*)d_in[9];
    const void*  src     = d_in[10];
    const void*  dst     = d_in[11];
    float* out = (float*)d_out;

    const int SMEM_N = (2 * WTILE + 2 * 128 * STW) * 4;   // 55296 B
    const int SMEM_F = (WTILE + 128 * STW) * 4;           // 27648 B
    cudaFuncSetAttribute((const void*)k_mma<true, true, true>,
                         cudaFuncAttributeMaxDynamicSharedMemorySize, SMEM_N);
    cudaFuncSetAttribute((const void*)k_mma<true, false, true>,
                         cudaFuncAttributeMaxDynamicSharedMemorySize, SMEM_N);
    cudaFuncSetAttribute((const void*)k_mma<false, false, false>,
                         cudaFuncAttributeMaxDynamicSharedMemorySize, SMEM_F);

    __half2*  xh;   cudaGetSymbolAddress((void**)&xh,   g_xh);
    __half2*  aggh; cudaGetSymbolAddress((void**)&aggh, g_aggh);
    __half2*  h1h;  cudaGetSymbolAddress((void**)&h1h,  g_h1h);
    __half2*  h2h;  cudaGetSymbolAddress((void**)&h2h,  g_h2h);
    unsigned* wt;   cudaGetSymbolAddress((void**)&wt,   g_wt);

    // --- prep: zero+cvt(embed,weights), bucket fill ---
    k_zero<<<(N_NODES * 32 + 255) / 256, 256>>>(ids_w, embed,
                                                W1_self, W1_neigh, W2_self, W2_neigh, W_fc);
    k_fill<<<(N_EDGES + 255) / 256, 256>>>(src, dst);

    const int AGG_BLOCKS = (N_NODES * 32 + 255) / 256;

    // --- Layer 1 ---
    k_agg<<<AGG_BLOCKS, 256>>>(xh, aggh);
    k_mma<true, true, true><<<NTILE, 256, SMEM_N>>>(
        xh, aggh, wt + 0 * WTILE, wt + 1 * WTILE, b1, h1h);

    // --- Layer 2 ---
    k_agg<<<AGG_BLOCKS, 256>>>(h1h, aggh);
    k_mma<true, false, true><<<NTILE, 256, SMEM_N>>>(
        h1h, aggh, wt + 2 * WTILE, wt + 3 * WTILE, b2, h2h);

    // --- Final linear (f32 output) ---
    k_mma<false, false, false><<<NTILE, 256, SMEM_F>>>(
        h2h, nullptr, wt + 4 * WTILE, nullptr, b_fc, out);
}